// round 2
// baseline (speedup 1.0000x reference)
#include <cuda_runtime.h>
#include <math.h>

#define BB 4
#define DIM 1024
#define NHH 4
#define HD 256
#define MAXP 2304
#define MASKN 2304
#define MAXLEN 3392
#define PPB 8
#define SMX_IT 14

typedef unsigned long long ull;

__device__ float g_X[(size_t)BB * MAXLEN * DIM];
__device__ float g_Y[(size_t)BB * MAXLEN * DIM];
__device__ float g_QKV[(size_t)BB * MAXLEN * 3 * DIM];
__device__ float g_H[(size_t)BB * MAXLEN * 4 * DIM];
__device__ float g_ATT[(size_t)BB * MAXLEN * DIM];
__device__ float g_S[(size_t)BB * NHH * MAXLEN * MAXLEN];
__device__ int   g_cnt[BB];
__device__ int   g_L[BB];
__device__ int   g_rc[BB * MAXP];
__device__ float g_dep[BB * MAXP];

__device__ __forceinline__ float gelu_f(float x) {
    return 0.5f * x * (1.0f + erff(x * 0.7071067811865475f));
}
__device__ __forceinline__ ull pk2(float lo, float hi) {
    ull r; asm("mov.b64 %0, {%1, %2};" : "=l"(r) : "f"(lo), "f"(hi)); return r;
}
__device__ __forceinline__ float2 upk2(ull v) {
    float2 r; asm("mov.b64 {%0, %1}, %2;" : "=f"(r.x), "=f"(r.y) : "l"(v)); return r;
}
__device__ __forceinline__ void fma2(ull& d, ull a, ull b) {
    asm("fma.rn.f32x2 %0, %1, %2, %0;" : "+l"(d) : "l"(a), "l"(b));
}

__device__ __forceinline__ float blk_red_sum(float v, float* sh) {
    int tid = threadIdx.x, lane = tid & 31, w = tid >> 5;
    #pragma unroll
    for (int o = 16; o > 0; o >>= 1) v += __shfl_xor_sync(0xffffffffu, v, o);
    if (lane == 0) sh[w] = v;
    __syncthreads();
    float r = sh[0] + sh[1] + sh[2] + sh[3] + sh[4] + sh[5] + sh[6] + sh[7];
    __syncthreads();
    return r;
}
__device__ __forceinline__ float blk_red_max(float v, float* sh) {
    int tid = threadIdx.x, lane = tid & 31, w = tid >> 5;
    #pragma unroll
    for (int o = 16; o > 0; o >>= 1) v = fmaxf(v, __shfl_xor_sync(0xffffffffu, v, o));
    if (lane == 0) sh[w] = v;
    __syncthreads();
    float r = fmaxf(fmaxf(fmaxf(sh[0], sh[1]), fmaxf(sh[2], sh[3])),
                    fmaxf(fmaxf(sh[4], sh[5]), fmaxf(sh[6], sh[7])));
    __syncthreads();
    return r;
}

#define MM_INNER(ASARR, BSARR)                                                    \
    _Pragma("unroll")                                                             \
    for (int kk = 0; kk < 16; kk++) {                                             \
        float4 a4 = *(const float4*)&ASARR[kk][ty * 4];                           \
        float4 b4 = *(const float4*)&BSARR[kk][tx * 4];                           \
        ull b01 = pk2(b4.x, b4.y), b23 = pk2(b4.z, b4.w);                         \
        ull aa;                                                                   \
        aa = pk2(a4.x, a4.x); fma2(acc[0][0], aa, b01); fma2(acc[0][1], aa, b23); \
        aa = pk2(a4.y, a4.y); fma2(acc[1][0], aa, b01); fma2(acc[1][1], aa, b23); \
        aa = pk2(a4.z, a4.z); fma2(acc[2][0], aa, b01); fma2(acc[2][1], aa, b23); \
        aa = pk2(a4.w, a4.w); fma2(acc[3][0], aa, b01); fma2(acc[3][1], aa, b23); \
    }

__global__ void scan_prompts(const int* __restrict__ maskp,
                             const float* __restrict__ depth) {
    int b = blockIdx.x;
    const int* m = maskp + b * MASKN;
    const float* dp = depth + b * MASKN;
    int tid = threadIdx.x, lane = tid & 31, w = tid >> 5;
    __shared__ int wsum[8];
    __shared__ int base;
    if (tid == 0) base = 0;
    __syncthreads();
    for (int c0 = 0; c0 < MASKN; c0 += 256) {
        int idx = c0 + tid;
        int pred = (m[idx] > 0) ? 1 : 0;
        unsigned bal = __ballot_sync(0xffffffffu, pred);
        if (lane == 0) wsum[w] = __popc(bal);
        __syncthreads();
        int woff = base;
        for (int ww = 0; ww < w; ww++) woff += wsum[ww];
        if (pred) {
            int pos = woff + __popc(bal & ((1u << lane) - 1u));
            g_rc[b * MAXP + pos] = idx;
            g_dep[b * MAXP + pos] = dp[idx];
        }
        __syncthreads();
        if (tid == 0) {
            int t = 0;
            for (int ww = 0; ww < 8; ww++) t += wsum[ww];
            base += t;
        }
        __syncthreads();
    }
    if (tid == 0) { g_cnt[b] = base; g_L[b] = 1025 + base; }
}

__global__ __launch_bounds__(256) void init_query(const float* __restrict__ img,
                                                  const float* __restrict__ gauss) {
    int t = blockIdx.x, b = blockIdx.y;
    int tid = threadIdx.x;
    float cx = 2.f * ((float)(t & 31) + 0.5f) / 32.f - 1.f;
    float cy = 2.f * ((float)(t >> 5) + 0.5f) / 32.f - 1.f;
    const float* ib = img + ((size_t)b * 1024 + t) * DIM;
    float* xr = g_X + ((size_t)b * MAXLEN + t) * DIM;
    #pragma unroll
    for (int p = 0; p < 2; p++) {
        int k = tid + p * 256;
        float vv = 6.283185307179586f * (cx * gauss[k] + cy * gauss[512 + k]);
        float sv, cv;
        sincosf(vv, &sv, &cv);
        xr[k] = ib[k] + sv;
        xr[k + 512] = ib[k + 512] + cv;
    }
}

__global__ __launch_bounds__(256) void prompt_rows(const float* __restrict__ gauss,
                                                   const float* __restrict__ w1,
                                                   const float* __restrict__ b1,
                                                   const float* __restrict__ w2,
                                                   const float* __restrict__ b2) {
    int b = blockIdx.y;
    int cnt = g_cnt[b];
    int j0 = blockIdx.x * PPB;
    if (j0 >= cnt) return;
    int na = cnt - j0; if (na > PPB) na = PPB;
    __shared__ float h[PPB][512];
    __shared__ float cxs[PPB], cys[PPB];
    int tid = threadIdx.x;
    if (tid < PPB) {
        float cx = 0.f, cy = 0.f;
        if (tid < na) {
            int rc = g_rc[b * MAXP + j0 + tid];
            cx = 2.f * ((float)(rc % 48) + 0.5f) / 48.f - 1.f;
            cy = 2.f * ((float)(rc / 48) + 0.5f) / 48.f - 1.f;
        }
        cxs[tid] = cx; cys[tid] = cy;
    }
    for (int e = tid; e < PPB * 512; e += 256) {
        int q = e >> 9, k = e & 511;
        float d = (q < na) ? g_dep[b * MAXP + j0 + q] : 0.f;
        h[q][k] = gelu_f(fmaf(d, w1[k], b1[k]));
    }
    __syncthreads();
    float* xr = g_X + ((size_t)b * MAXLEN + 1025 + j0) * DIM;
    #pragma unroll
    for (int p = 0; p < 4; p++) {
        int c = tid + p * 256;
        int kcol = c & 511;
        float g0 = gauss[kcol], g1 = gauss[512 + kcol];
        float bb = b2[c];
        float acc[PPB];
        #pragma unroll
        for (int q = 0; q < PPB; q++) {
            float vv = 6.283185307179586f * (cxs[q] * g0 + cys[q] * g1);
            acc[q] = bb + ((c < 512) ? sinf(vv) : cosf(vv));
        }
        for (int k = 0; k < 512; k++) {
            float wv = w2[k * 1024 + c];
            #pragma unroll
            for (int q = 0; q < PPB; q++) acc[q] = fmaf(h[q][k], wv, acc[q]);
        }
        for (int q = 0; q < na; q++) xr[(size_t)q * DIM + c] = acc[q];
    }
}

__global__ void sep_kernel(const float* __restrict__ sep) {
    int b = blockIdx.x; int tid = threadIdx.x;
    float* xr = g_X + ((size_t)b * MAXLEN + 1024) * DIM;
    #pragma unroll
    for (int p = 0; p < 4; p++) xr[tid + p * 256] = sep[tid + p * 256];
}

__global__ __launch_bounds__(256) void ln_kernel(const float* __restrict__ w,
                                                 const float* __restrict__ bs) {
    int t = blockIdx.x, b = blockIdx.y;
    if (t >= g_L[b]) return;
    __shared__ float sh[8];
    const float* xr = g_X + ((size_t)b * MAXLEN + t) * DIM;
    float* yr = g_Y + ((size_t)b * MAXLEN + t) * DIM;
    int tid = threadIdx.x;
    float4 v = ((const float4*)xr)[tid];
    float s = blk_red_sum(v.x + v.y + v.z + v.w, sh);
    float m = s * (1.f / 1024.f);
    float4 dv = make_float4(v.x - m, v.y - m, v.z - m, v.w - m);
    float vs = blk_red_sum(dv.x * dv.x + dv.y * dv.y + dv.z * dv.z + dv.w * dv.w, sh);
    float rs = rsqrtf(vs * (1.f / 1024.f) + 1e-5f);
    float4 wv = ((const float4*)w)[tid];
    float4 bv = ((const float4*)bs)[tid];
    ((float4*)yr)[tid] = make_float4(dv.x * rs * wv.x + bv.x, dv.y * rs * wv.y + bv.y,
                                     dv.z * rs * wv.z + bv.z, dv.w * rs * wv.w + bv.w);
}

/* C = op(A[K] @ W + bias); MODE 0 store, 1 gelu, 2 += (residual) */
template <int MODE>
__global__ __launch_bounds__(256) void gemm_kernel(const float* __restrict__ A,
                                                   const float* __restrict__ W,
                                                   const float* __restrict__ bias,
                                                   float* __restrict__ C,
                                                   int K, int lda, int ldw, int ldc) {
    int row0 = blockIdx.y * 64;
    int b = row0 / MAXLEN;
    int local = row0 - b * MAXLEN;
    int L = g_L[b];
    if (local >= L) return;
    int col0 = blockIdx.x * 64;
    int tid = threadIdx.x;
    int tx = tid & 15, ty = tid >> 4;
    __shared__ float As[16][68];
    __shared__ float Bs[16][64];
    ull acc[4][2];
    ull z = pk2(0.f, 0.f);
    #pragma unroll
    for (int i = 0; i < 4; i++) { acc[i][0] = z; acc[i][1] = z; }
    const float* Ag = A + (size_t)row0 * lda;
    int lk = tid & 15, lr = tid >> 4;
    int bkk = tid >> 4, bc = (tid & 15) * 4;
    for (int k0 = 0; k0 < K; k0 += 16) {
        #pragma unroll
        for (int rr = 0; rr < 4; rr++)
            As[lk][lr + rr * 16] = Ag[(size_t)(lr + rr * 16) * lda + k0 + lk];
        *(float4*)&Bs[bkk][bc] = *(const float4*)&W[(size_t)(k0 + bkk) * ldw + col0 + bc];
        __syncthreads();
        MM_INNER(As, Bs)
        __syncthreads();
    }
    float4 bb = *(const float4*)&bias[col0 + tx * 4];
    #pragma unroll
    for (int i = 0; i < 4; i++) {
        if (local + ty * 4 + i >= L) continue;
        float2 lo = upk2(acc[i][0]);
        float2 hi = upk2(acc[i][1]);
        float4 o = make_float4(lo.x + bb.x, lo.y + bb.y, hi.x + bb.z, hi.y + bb.w);
        float* cr = C + (size_t)(row0 + ty * 4 + i) * ldc + col0 + tx * 4;
        if (MODE == 1) {
            o.x = gelu_f(o.x); o.y = gelu_f(o.y); o.z = gelu_f(o.z); o.w = gelu_f(o.w);
            *(float4*)cr = o;
        } else if (MODE == 2) {
            float4 old = *(const float4*)cr;
            o.x += old.x; o.y += old.y; o.z += old.z; o.w += old.w;
            *(float4*)cr = o;
        } else {
            *(float4*)cr = o;
        }
    }
}

__global__ __launch_bounds__(256) void scores_kernel() {
    int bh = blockIdx.z; int b = bh >> 2, h = bh & 3;
    int L = g_L[b];
    int n0 = blockIdx.y * 64, m0 = blockIdx.x * 64;
    if (n0 >= L || m0 >= L) return;
    const float* Qb = g_QKV + (size_t)b * MAXLEN * 3072 + h * HD;
    const float* Kb = Qb + 1024;
    __shared__ float As[16][68];
    __shared__ float Bs[16][68];
    int tid = threadIdx.x, tx = tid & 15, ty = tid >> 4;
    ull acc[4][2];
    ull z = pk2(0.f, 0.f);
    #pragma unroll
    for (int i = 0; i < 4; i++) { acc[i][0] = z; acc[i][1] = z; }
    int lk = tid & 15, lr = tid >> 4;
    for (int d0 = 0; d0 < HD; d0 += 16) {
        #pragma unroll
        for (int rr = 0; rr < 4; rr++) {
            int r = lr + rr * 16;
            As[lk][r] = Qb[(size_t)(n0 + r) * 3072 + d0 + lk];
            Bs[lk][r] = Kb[(size_t)(m0 + r) * 3072 + d0 + lk];
        }
        __syncthreads();
        MM_INNER(As, Bs)
        __syncthreads();
    }
    #pragma unroll
    for (int i = 0; i < 4; i++) {
        int n = n0 + ty * 4 + i;
        if (n >= L) continue;
        float2 lo = upk2(acc[i][0]);
        float2 hi = upk2(acc[i][1]);
        float vv[4] = {lo.x * 0.0625f, lo.y * 0.0625f, hi.x * 0.0625f, hi.y * 0.0625f};
        int m = m0 + tx * 4;
        float* sr = g_S + (size_t)bh * MAXLEN * MAXLEN + (size_t)n * MAXLEN + m;
        if (m + 3 < L) {
            *(float4*)sr = make_float4(vv[0], vv[1], vv[2], vv[3]);
        } else {
            for (int e = 0; e < 4; e++) if (m + e < L) sr[e] = vv[e];
        }
    }
}

__global__ __launch_bounds__(256) void softmax_kernel() {
    int n = blockIdx.x, h = blockIdx.y, b = blockIdx.z;
    int L = g_L[b];
    if (n >= L) return;
    __shared__ float sh[8];
    float* sr = g_S + (size_t)(b * NHH + h) * MAXLEN * MAXLEN + (size_t)n * MAXLEN;
    int tid = threadIdx.x;
    float v[SMX_IT];
    float mx = -3e38f;
    #pragma unroll
    for (int i = 0; i < SMX_IT; i++) {
        int m = tid + i * 256;
        v[i] = (m < L) ? sr[m] : -3e38f;
        mx = fmaxf(mx, v[i]);
    }
    mx = blk_red_max(mx, sh);
    float sum = 0.f;
    #pragma unroll
    for (int i = 0; i < SMX_IT; i++) { v[i] = expf(v[i] - mx); sum += v[i]; }
    sum = blk_red_sum(sum, sh);
    float inv = 1.f / sum;
    #pragma unroll
    for (int i = 0; i < SMX_IT; i++) {
        int m = tid + i * 256;
        if (m < L) sr[m] = v[i] * inv;
    }
}

__global__ __launch_bounds__(256) void av_kernel() {
    int bh = blockIdx.z; int b = bh >> 2, h = bh & 3;
    int L = g_L[b];
    int n0 = blockIdx.y * 64;
    if (n0 >= L) return;
    int col0 = blockIdx.x * 64;
    const float* P = g_S + (size_t)bh * MAXLEN * MAXLEN;
    const float* V = g_QKV + (size_t)b * MAXLEN * 3072 + 2048 + h * HD;
    float* C = g_ATT + (size_t)b * MAXLEN * DIM + h * HD;
    __shared__ float As[16][68];
    __shared__ float Bs[16][64];
    int tid = threadIdx.x, tx = tid & 15, ty = tid >> 4;
    ull acc[4][2];
    ull z = pk2(0.f, 0.f);
    #pragma unroll
    for (int i = 0; i < 4; i++) { acc[i][0] = z; acc[i][1] = z; }
    int lk = tid & 15, lr = tid >> 4;
    int bkk = tid >> 4, bc = (tid & 15) * 4;
    int Kpad = (L + 15) & ~15;
    for (int k0 = 0; k0 < Kpad; k0 += 16) {
        #pragma unroll
        for (int rr = 0; rr < 4; rr++) {
            int r = lr + rr * 16;
            As[lk][r] = (k0 + lk < L) ? P[(size_t)(n0 + r) * MAXLEN + k0 + lk] : 0.f;
        }
        float4 bv = make_float4(0.f, 0.f, 0.f, 0.f);
        if (k0 + bkk < L) bv = *(const float4*)&V[(size_t)(k0 + bkk) * 3072 + col0 + bc];
        *(float4*)&Bs[bkk][bc] = bv;
        __syncthreads();
        MM_INNER(As, Bs)
        __syncthreads();
    }
    #pragma unroll
    for (int i = 0; i < 4; i++) {
        int n = n0 + ty * 4 + i;
        if (n >= L) continue;
        float2 lo = upk2(acc[i][0]);
        float2 hi = upk2(acc[i][1]);
        *(float4*)&C[(size_t)n * DIM + col0 + tx * 4] =
            make_float4(lo.x, lo.y, hi.x, hi.y);
    }
}

__global__ void out_copy(const float* __restrict__ img, float* __restrict__ out) {
    int t = blockIdx.x, b = blockIdx.y;
    int tid = threadIdx.x;
    const float* src = (g_cnt[b] == 0)
        ? img + ((size_t)b * 1024 + t) * DIM
        : g_X + ((size_t)b * MAXLEN + t) * DIM;
    float4* o = (float4*)(out + ((size_t)b * 1024 + t) * DIM);
    o[tid] = ((const float4*)src)[tid];
}

extern "C" void kernel_launch(void* const* d_in, const int* in_sizes, int n_in,
                              void* d_out, int out_size) {
    const float* img   = (const float*)d_in[0];
    const float* depth = (const float*)d_in[1];
    const int*   mask  = (const int*)d_in[2];
    const float* gauss = (const float*)d_in[5];
    const float* w1    = (const float*)d_in[6];
    const float* b1    = (const float*)d_in[7];
    const float* w2    = (const float*)d_in[8];
    const float* b2    = (const float*)d_in[9];
    const float* sep   = (const float*)d_in[10];
    const float* ln1w  = (const float*)d_in[11];
    const float* ln1b  = (const float*)d_in[12];
    const float* qkvw  = (const float*)d_in[13];
    const float* qkvb  = (const float*)d_in[14];
    const float* projw = (const float*)d_in[15];
    const float* projb = (const float*)d_in[16];
    const float* ln2w  = (const float*)d_in[17];
    const float* ln2b  = (const float*)d_in[18];
    const float* mw1   = (const float*)d_in[19];
    const float* mb1   = (const float*)d_in[20];
    const float* mw2   = (const float*)d_in[21];
    const float* mb2   = (const float*)d_in[22];
    float* out = (float*)d_out;

    float *pY, *pQKV, *pH, *pATT, *pX;
    cudaGetSymbolAddress((void**)&pX, g_X);
    cudaGetSymbolAddress((void**)&pY, g_Y);
    cudaGetSymbolAddress((void**)&pQKV, g_QKV);
    cudaGetSymbolAddress((void**)&pH, g_H);
    cudaGetSymbolAddress((void**)&pATT, g_ATT);

    const int RT = (BB * MAXLEN) / 64;  /* 212 row tiles */
    const int LT = MAXLEN / 64;         /* 53 */

    scan_prompts<<<BB, 256>>>(mask, depth);
    init_query<<<dim3(1024, BB), 256>>>(img, gauss);
    prompt_rows<<<dim3(MAXP / PPB, BB), 256>>>(gauss, w1, b1, w2, b2);

    for (int i = 0; i < 2; i++) {
        sep_kernel<<<BB, 256>>>(sep + (size_t)i * DIM);
        ln_kernel<<<dim3(MAXLEN, BB), 256>>>(ln1w + i * DIM, ln1b + i * DIM);
        gemm_kernel<0><<<dim3(48, RT), 256>>>(pY, qkvw + (size_t)i * DIM * 3 * DIM,
                                              qkvb + i * 3 * DIM, pQKV,
                                              1024, 1024, 3072, 3072);
        scores_kernel<<<dim3(LT, LT, BB * NHH), 256>>>();
        softmax_kernel<<<dim3(MAXLEN, NHH, BB), 256>>>();
        av_kernel<<<dim3(HD / 64, LT, BB * NHH), 256>>>();
        gemm_kernel<2><<<dim3(16, RT), 256>>>(pATT, projw + (size_t)i * DIM * DIM,
                                              projb + i * DIM, pX,
                                              1024, 1024, 1024, 1024);
        ln_kernel<<<dim3(MAXLEN, BB), 256>>>(ln2w + i * DIM, ln2b + i * DIM);
        gemm_kernel<1><<<dim3(64, RT), 256>>>(pY, mw1 + (size_t)i * DIM * 4096,
                                              mb1 + i * 4096, pH,
                                              1024, 1024, 4096, 4096);
        gemm_kernel<2><<<dim3(16, RT), 256>>>(pH, mw2 + (size_t)i * 4096 * DIM,
                                              mb2 + i * DIM, pX,
                                              4096, 4096, 1024, 1024);
    }
    out_copy<<<dim3(1024, BB), 256>>>(img, out);
}

// round 3
// speedup vs baseline: 1.0012x; 1.0012x over previous
#include <cuda_runtime.h>
#include <math.h>

#define BB 4
#define DIM 1024
#define NHH 4
#define HD 256
#define MAXP 2304
#define MASKN 2304
#define MAXLEN 3392
#define PPB 8
#define SMX_IT 14

typedef unsigned long long ull;

__device__ float g_X[(size_t)BB * MAXLEN * DIM];
__device__ float g_Y[(size_t)BB * MAXLEN * DIM];
__device__ float g_QKV[(size_t)BB * MAXLEN * 3 * DIM];
__device__ float g_H[(size_t)BB * MAXLEN * 4 * DIM];
__device__ float g_ATT[(size_t)BB * MAXLEN * DIM];
__device__ float g_S[(size_t)BB * NHH * MAXLEN * MAXLEN];
__device__ int   g_cnt[BB];
__device__ int   g_L[BB];
__device__ int   g_rc[BB * MAXP];
__device__ float g_dep[BB * MAXP];

__device__ __forceinline__ float gelu_f(float x) {
    return 0.5f * x * (1.0f + erff(x * 0.7071067811865475f));
}
__device__ __forceinline__ ull pk2(float lo, float hi) {
    ull r; asm("mov.b64 %0, {%1, %2};" : "=l"(r) : "f"(lo), "f"(hi)); return r;
}
__device__ __forceinline__ float2 upk2(ull v) {
    float2 r; asm("mov.b64 {%0, %1}, %2;" : "=f"(r.x), "=f"(r.y) : "l"(v)); return r;
}
__device__ __forceinline__ void fma2(ull& d, ull a, ull b) {
    asm("fma.rn.f32x2 %0, %1, %2, %0;" : "+l"(d) : "l"(a), "l"(b));
}

__device__ __forceinline__ float blk_red_sum(float v, float* sh) {
    int tid = threadIdx.x, lane = tid & 31, w = tid >> 5;
    #pragma unroll
    for (int o = 16; o > 0; o >>= 1) v += __shfl_xor_sync(0xffffffffu, v, o);
    if (lane == 0) sh[w] = v;
    __syncthreads();
    float r = sh[0] + sh[1] + sh[2] + sh[3] + sh[4] + sh[5] + sh[6] + sh[7];
    __syncthreads();
    return r;
}
__device__ __forceinline__ float blk_red_max(float v, float* sh) {
    int tid = threadIdx.x, lane = tid & 31, w = tid >> 5;
    #pragma unroll
    for (int o = 16; o > 0; o >>= 1) v = fmaxf(v, __shfl_xor_sync(0xffffffffu, v, o));
    if (lane == 0) sh[w] = v;
    __syncthreads();
    float r = fmaxf(fmaxf(fmaxf(sh[0], sh[1]), fmaxf(sh[2], sh[3])),
                    fmaxf(fmaxf(sh[4], sh[5]), fmaxf(sh[6], sh[7])));
    __syncthreads();
    return r;
}

#define MM_INNER(ASARR, BSARR)                                                    \
    _Pragma("unroll")                                                             \
    for (int kk = 0; kk < 16; kk++) {                                             \
        float4 a4 = *(const float4*)&ASARR[kk][ty * 4];                           \
        float4 b4 = *(const float4*)&BSARR[kk][tx * 4];                           \
        ull b01 = pk2(b4.x, b4.y), b23 = pk2(b4.z, b4.w);                         \
        ull aa;                                                                   \
        aa = pk2(a4.x, a4.x); fma2(acc[0][0], aa, b01); fma2(acc[0][1], aa, b23); \
        aa = pk2(a4.y, a4.y); fma2(acc[1][0], aa, b01); fma2(acc[1][1], aa, b23); \
        aa = pk2(a4.z, a4.z); fma2(acc[2][0], aa, b01); fma2(acc[2][1], aa, b23); \
        aa = pk2(a4.w, a4.w); fma2(acc[3][0], aa, b01); fma2(acc[3][1], aa, b23); \
    }

__global__ void scan_prompts(const int* __restrict__ maskp,
                             const float* __restrict__ depth) {
    int b = blockIdx.x;
    const int* m = maskp + b * MASKN;
    const float* dp = depth + b * MASKN;
    int tid = threadIdx.x, lane = tid & 31, w = tid >> 5;
    __shared__ int wsum[8];
    __shared__ int base;
    if (tid == 0) base = 0;
    __syncthreads();
    for (int c0 = 0; c0 < MASKN; c0 += 256) {
        int idx = c0 + tid;
        int pred = (m[idx] > 0) ? 1 : 0;
        unsigned bal = __ballot_sync(0xffffffffu, pred);
        if (lane == 0) wsum[w] = __popc(bal);
        __syncthreads();
        int woff = base;
        for (int ww = 0; ww < w; ww++) woff += wsum[ww];
        if (pred) {
            int pos = woff + __popc(bal & ((1u << lane) - 1u));
            g_rc[b * MAXP + pos] = idx;
            g_dep[b * MAXP + pos] = dp[idx];
        }
        __syncthreads();
        if (tid == 0) {
            int t = 0;
            for (int ww = 0; ww < 8; ww++) t += wsum[ww];
            base += t;
        }
        __syncthreads();
    }
    if (tid == 0) { g_cnt[b] = base; g_L[b] = 1025 + base; }
}

__global__ __launch_bounds__(256) void init_query(const float* __restrict__ img,
                                                  const float* __restrict__ gauss) {
    int t = blockIdx.x, b = blockIdx.y;
    int tid = threadIdx.x;
    float cx = 2.f * ((float)(t & 31) + 0.5f) / 32.f - 1.f;
    float cy = 2.f * ((float)(t >> 5) + 0.5f) / 32.f - 1.f;
    const float* ib = img + ((size_t)b * 1024 + t) * DIM;
    float* xr = g_X + ((size_t)b * MAXLEN + t) * DIM;
    #pragma unroll
    for (int p = 0; p < 2; p++) {
        int k = tid + p * 256;
        float vv = 6.283185307179586f * (cx * gauss[k] + cy * gauss[512 + k]);
        float sv, cv;
        sincosf(vv, &sv, &cv);
        xr[k] = ib[k] + sv;
        xr[k + 512] = ib[k + 512] + cv;
    }
}

__global__ __launch_bounds__(256) void prompt_rows(const float* __restrict__ gauss,
                                                   const float* __restrict__ w1,
                                                   const float* __restrict__ b1,
                                                   const float* __restrict__ w2,
                                                   const float* __restrict__ b2) {
    int b = blockIdx.y;
    int cnt = g_cnt[b];
    int j0 = blockIdx.x * PPB;
    if (j0 >= cnt) return;
    int na = cnt - j0; if (na > PPB) na = PPB;
    __shared__ float h[PPB][512];
    __shared__ float cxs[PPB], cys[PPB];
    int tid = threadIdx.x;
    if (tid < PPB) {
        float cx = 0.f, cy = 0.f;
        if (tid < na) {
            int rc = g_rc[b * MAXP + j0 + tid];
            cx = 2.f * ((float)(rc % 48) + 0.5f) / 48.f - 1.f;
            cy = 2.f * ((float)(rc / 48) + 0.5f) / 48.f - 1.f;
        }
        cxs[tid] = cx; cys[tid] = cy;
    }
    for (int e = tid; e < PPB * 512; e += 256) {
        int q = e >> 9, k = e & 511;
        float d = (q < na) ? g_dep[b * MAXP + j0 + q] : 0.f;
        h[q][k] = gelu_f(fmaf(d, w1[k], b1[k]));
    }
    __syncthreads();
    float* xr = g_X + ((size_t)b * MAXLEN + 1025 + j0) * DIM;
    #pragma unroll
    for (int p = 0; p < 4; p++) {
        int c = tid + p * 256;
        int kcol = c & 511;
        float g0 = gauss[kcol], g1 = gauss[512 + kcol];
        float bb = b2[c];
        float acc[PPB];
        #pragma unroll
        for (int q = 0; q < PPB; q++) {
            float vv = 6.283185307179586f * (cxs[q] * g0 + cys[q] * g1);
            acc[q] = bb + ((c < 512) ? sinf(vv) : cosf(vv));
        }
        for (int k = 0; k < 512; k++) {
            float wv = w2[k * 1024 + c];
            #pragma unroll
            for (int q = 0; q < PPB; q++) acc[q] = fmaf(h[q][k], wv, acc[q]);
        }
        for (int q = 0; q < na; q++) xr[(size_t)q * DIM + c] = acc[q];
    }
}

__global__ void sep_kernel(const float* __restrict__ sep) {
    int b = blockIdx.x; int tid = threadIdx.x;
    float* xr = g_X + ((size_t)b * MAXLEN + 1024) * DIM;
    #pragma unroll
    for (int p = 0; p < 4; p++) xr[tid + p * 256] = sep[tid + p * 256];
}

__global__ __launch_bounds__(256) void ln_kernel(const float* __restrict__ w,
                                                 const float* __restrict__ bs) {
    int t = blockIdx.x, b = blockIdx.y;
    if (t >= g_L[b]) return;
    __shared__ float sh[8];
    const float* xr = g_X + ((size_t)b * MAXLEN + t) * DIM;
    float* yr = g_Y + ((size_t)b * MAXLEN + t) * DIM;
    int tid = threadIdx.x;
    float4 v = ((const float4*)xr)[tid];
    float s = blk_red_sum(v.x + v.y + v.z + v.w, sh);
    float m = s * (1.f / 1024.f);
    float4 dv = make_float4(v.x - m, v.y - m, v.z - m, v.w - m);
    float vs = blk_red_sum(dv.x * dv.x + dv.y * dv.y + dv.z * dv.z + dv.w * dv.w, sh);
    float rs = rsqrtf(vs * (1.f / 1024.f) + 1e-5f);
    float4 wv = ((const float4*)w)[tid];
    float4 bv = ((const float4*)bs)[tid];
    ((float4*)yr)[tid] = make_float4(dv.x * rs * wv.x + bv.x, dv.y * rs * wv.y + bv.y,
                                     dv.z * rs * wv.z + bv.z, dv.w * rs * wv.w + bv.w);
}

/* C = op(A[K] @ W + bias); MODE 0 store, 1 gelu, 2 += (residual) */
template <int MODE>
__global__ __launch_bounds__(256) void gemm_kernel(const float* __restrict__ A,
                                                   const float* __restrict__ W,
                                                   const float* __restrict__ bias,
                                                   float* __restrict__ C,
                                                   int K, int lda, int ldw, int ldc) {
    int row0 = blockIdx.y * 64;
    int b = row0 / MAXLEN;
    int local = row0 - b * MAXLEN;
    int L = g_L[b];
    if (local >= L) return;
    int col0 = blockIdx.x * 64;
    int tid = threadIdx.x;
    int tx = tid & 15, ty = tid >> 4;
    __shared__ float As[16][68];
    __shared__ float Bs[16][64];
    ull acc[4][2];
    ull z = pk2(0.f, 0.f);
    #pragma unroll
    for (int i = 0; i < 4; i++) { acc[i][0] = z; acc[i][1] = z; }
    const float* Ag = A + (size_t)row0 * lda;
    int lk = tid & 15, lr = tid >> 4;
    int bkk = tid >> 4, bc = (tid & 15) * 4;
    for (int k0 = 0; k0 < K; k0 += 16) {
        #pragma unroll
        for (int rr = 0; rr < 4; rr++)
            As[lk][lr + rr * 16] = Ag[(size_t)(lr + rr * 16) * lda + k0 + lk];
        *(float4*)&Bs[bkk][bc] = *(const float4*)&W[(size_t)(k0 + bkk) * ldw + col0 + bc];
        __syncthreads();
        MM_INNER(As, Bs)
        __syncthreads();
    }
    float4 bb = *(const float4*)&bias[col0 + tx * 4];
    #pragma unroll
    for (int i = 0; i < 4; i++) {
        if (local + ty * 4 + i >= L) continue;
        float2 lo = upk2(acc[i][0]);
        float2 hi = upk2(acc[i][1]);
        float4 o = make_float4(lo.x + bb.x, lo.y + bb.y, hi.x + bb.z, hi.y + bb.w);
        float* cr = C + (size_t)(row0 + ty * 4 + i) * ldc + col0 + tx * 4;
        if (MODE == 1) {
            o.x = gelu_f(o.x); o.y = gelu_f(o.y); o.z = gelu_f(o.z); o.w = gelu_f(o.w);
            *(float4*)cr = o;
        } else if (MODE == 2) {
            float4 old = *(const float4*)cr;
            o.x += old.x; o.y += old.y; o.z += old.z; o.w += old.w;
            *(float4*)cr = o;
        } else {
            *(float4*)cr = o;
        }
    }
}

__global__ __launch_bounds__(256) void scores_kernel() {
    int bh = blockIdx.z; int b = bh >> 2, h = bh & 3;
    int L = g_L[b];
    int n0 = blockIdx.y * 64, m0 = blockIdx.x * 64;
    if (n0 >= L || m0 >= L) return;
    const float* Qb = g_QKV + (size_t)b * MAXLEN * 3072 + h * HD;
    const float* Kb = Qb + 1024;
    __shared__ float As[16][68];
    __shared__ float Bs[16][68];
    int tid = threadIdx.x, tx = tid & 15, ty = tid >> 4;
    ull acc[4][2];
    ull z = pk2(0.f, 0.f);
    #pragma unroll
    for (int i = 0; i < 4; i++) { acc[i][0] = z; acc[i][1] = z; }
    int lk = tid & 15, lr = tid >> 4;
    for (int d0 = 0; d0 < HD; d0 += 16) {
        #pragma unroll
        for (int rr = 0; rr < 4; rr++) {
            int r = lr + rr * 16;
            As[lk][r] = Qb[(size_t)(n0 + r) * 3072 + d0 + lk];
            Bs[lk][r] = Kb[(size_t)(m0 + r) * 3072 + d0 + lk];
        }
        __syncthreads();
        MM_INNER(As, Bs)
        __syncthreads();
    }
    #pragma unroll
    for (int i = 0; i < 4; i++) {
        int n = n0 + ty * 4 + i;
        if (n >= L) continue;
        float2 lo = upk2(acc[i][0]);
        float2 hi = upk2(acc[i][1]);
        float vv[4] = {lo.x * 0.0625f, lo.y * 0.0625f, hi.x * 0.0625f, hi.y * 0.0625f};
        int m = m0 + tx * 4;
        float* sr = g_S + (size_t)bh * MAXLEN * MAXLEN + (size_t)n * MAXLEN + m;
        if (m + 3 < L) {
            *(float4*)sr = make_float4(vv[0], vv[1], vv[2], vv[3]);
        } else {
            for (int e = 0; e < 4; e++) if (m + e < L) sr[e] = vv[e];
        }
    }
}

__global__ __launch_bounds__(256) void softmax_kernel() {
    int n = blockIdx.x, h = blockIdx.y, b = blockIdx.z;
    int L = g_L[b];
    if (n >= L) return;
    __shared__ float sh[8];
    float* sr = g_S + (size_t)(b * NHH + h) * MAXLEN * MAXLEN + (size_t)n * MAXLEN;
    int tid = threadIdx.x;
    float v[SMX_IT];
    float mx = -3e38f;
    #pragma unroll
    for (int i = 0; i < SMX_IT; i++) {
        int m = tid + i * 256;
        v[i] = (m < L) ? sr[m] : -3e38f;
        mx = fmaxf(mx, v[i]);
    }
    mx = blk_red_max(mx, sh);
    float sum = 0.f;
    #pragma unroll
    for (int i = 0; i < SMX_IT; i++) { v[i] = expf(v[i] - mx); sum += v[i]; }
    sum = blk_red_sum(sum, sh);
    float inv = 1.f / sum;
    #pragma unroll
    for (int i = 0; i < SMX_IT; i++) {
        int m = tid + i * 256;
        if (m < L) sr[m] = v[i] * inv;
    }
}

__global__ __launch_bounds__(256) void av_kernel() {
    int bh = blockIdx.z; int b = bh >> 2, h = bh & 3;
    int L = g_L[b];
    int n0 = blockIdx.y * 64;
    if (n0 >= L) return;
    int col0 = blockIdx.x * 64;
    const float* P = g_S + (size_t)bh * MAXLEN * MAXLEN;
    const float* V = g_QKV + (size_t)b * MAXLEN * 3072 + 2048 + h * HD;
    float* C = g_ATT + (size_t)b * MAXLEN * DIM + h * HD;
    __shared__ float As[16][68];
    __shared__ float Bs[16][64];
    int tid = threadIdx.x, tx = tid & 15, ty = tid >> 4;
    ull acc[4][2];
    ull z = pk2(0.f, 0.f);
    #pragma unroll
    for (int i = 0; i < 4; i++) { acc[i][0] = z; acc[i][1] = z; }
    int lk = tid & 15, lr = tid >> 4;
    int bkk = tid >> 4, bc = (tid & 15) * 4;
    int Kpad = (L + 15) & ~15;
    for (int k0 = 0; k0 < Kpad; k0 += 16) {
        #pragma unroll
        for (int rr = 0; rr < 4; rr++) {
            int r = lr + rr * 16;
            As[lk][r] = (k0 + lk < L) ? P[(size_t)(n0 + r) * MAXLEN + k0 + lk] : 0.f;
        }
        float4 bv = make_float4(0.f, 0.f, 0.f, 0.f);
        if (k0 + bkk < L) bv = *(const float4*)&V[(size_t)(k0 + bkk) * 3072 + col0 + bc];
        *(float4*)&Bs[bkk][bc] = bv;
        __syncthreads();
        MM_INNER(As, Bs)
        __syncthreads();
    }
    #pragma unroll
    for (int i = 0; i < 4; i++) {
        int n = n0 + ty * 4 + i;
        if (n >= L) continue;
        float2 lo = upk2(acc[i][0]);
        float2 hi = upk2(acc[i][1]);
        *(float4*)&C[(size_t)n * DIM + col0 + tx * 4] =
            make_float4(lo.x, lo.y, hi.x, hi.y);
    }
}

__global__ void out_copy(const float* __restrict__ img, float* __restrict__ out) {
    int t = blockIdx.x, b = blockIdx.y;
    int tid = threadIdx.x;
    const float* src = (g_cnt[b] == 0)
        ? img + ((size_t)b * 1024 + t) * DIM
        : g_X + ((size_t)b * MAXLEN + t) * DIM;
    float4* o = (float4*)(out + ((size_t)b * 1024 + t) * DIM);
    o[tid] = ((const float4*)src)[tid];
}

extern "C" void kernel_launch(void* const* d_in, const int* in_sizes, int n_in,
                              void* d_out, int out_size) {
    const float* img   = (const float*)d_in[0];
    const float* depth = (const float*)d_in[1];
    const int*   mask  = (const int*)d_in[2];
    const float* gauss = (const float*)d_in[5];
    const float* w1    = (const float*)d_in[6];
    const float* b1    = (const float*)d_in[7];
    const float* w2    = (const float*)d_in[8];
    const float* b2    = (const float*)d_in[9];
    const float* sep   = (const float*)d_in[10];
    const float* ln1w  = (const float*)d_in[11];
    const float* ln1b  = (const float*)d_in[12];
    const float* qkvw  = (const float*)d_in[13];
    const float* qkvb  = (const float*)d_in[14];
    const float* projw = (const float*)d_in[15];
    const float* projb = (const float*)d_in[16];
    const float* ln2w  = (const float*)d_in[17];
    const float* ln2b  = (const float*)d_in[18];
    const float* mw1   = (const float*)d_in[19];
    const float* mb1   = (const float*)d_in[20];
    const float* mw2   = (const float*)d_in[21];
    const float* mb2   = (const float*)d_in[22];
    float* out = (float*)d_out;

    float *pY, *pQKV, *pH, *pATT, *pX;
    cudaGetSymbolAddress((void**)&pX, g_X);
    cudaGetSymbolAddress((void**)&pY, g_Y);
    cudaGetSymbolAddress((void**)&pQKV, g_QKV);
    cudaGetSymbolAddress((void**)&pH, g_H);
    cudaGetSymbolAddress((void**)&pATT, g_ATT);

    const int RT = (BB * MAXLEN) / 64;  /* 212 row tiles */
    const int LT = MAXLEN / 64;         /* 53 */

    scan_prompts<<<BB, 256>>>(mask, depth);
    init_query<<<dim3(1024, BB), 256>>>(img, gauss);
    prompt_rows<<<dim3(MAXP / PPB, BB), 256>>>(gauss, w1, b1, w2, b2);

    for (int i = 0; i < 2; i++) {
        sep_kernel<<<BB, 256>>>(sep + (size_t)i * DIM);
        ln_kernel<<<dim3(MAXLEN, BB), 256>>>(ln1w + i * DIM, ln1b + i * DIM);
        gemm_kernel<0><<<dim3(48, RT), 256>>>(pY, qkvw + (size_t)i * DIM * 3 * DIM,
                                              qkvb + i * 3 * DIM, pQKV,
                                              1024, 1024, 3072, 3072);
        scores_kernel<<<dim3(LT, LT, BB * NHH), 256>>>();
        softmax_kernel<<<dim3(MAXLEN, NHH, BB), 256>>>();
        av_kernel<<<dim3(HD / 64, LT, BB * NHH), 256>>>();
        gemm_kernel<2><<<dim3(16, RT), 256>>>(pATT, projw + (size_t)i * DIM * DIM,
                                              projb + i * DIM, pX,
                                              1024, 1024, 1024, 1024);
        ln_kernel<<<dim3(MAXLEN, BB), 256>>>(ln2w + i * DIM, ln2b + i * DIM);
        gemm_kernel<1><<<dim3(64, RT), 256>>>(pY, mw1 + (size_t)i * DIM * 4096,
                                              mb1 + i * 4096, pH,
                                              1024, 1024, 4096, 4096);
        gemm_kernel<2><<<dim3(16, RT), 256>>>(pH, mw2 + (size_t)i * 4096 * DIM,
                                              mb2 + i * DIM, pX,
                                              4096, 4096, 1024, 1024);
    }
    out_copy<<<dim3(1024, BB), 256>>>(img, out);
}

// round 13
// speedup vs baseline: 2.2790x; 2.2762x over previous
#include <cuda_runtime.h>
#include <cuda_bf16.h>
#include <math.h>
#include <stdint.h>

#define BB 4
#define DIM 1024
#define NHH 4
#define HD 256
#define MAXP 2304
#define MASKN 2304
#define MAXLEN 3584
#define RTPB 28
#define PPB 8
#define SMX_IT 14
#define WLAYER 12582912

typedef unsigned int u32;
typedef __nv_bfloat16 bf16;

__device__ float g_X[(size_t)BB * MAXLEN * DIM];
__device__ bf16  g_Yh[(size_t)BB * MAXLEN * DIM];
__device__ bf16  g_Yl[(size_t)BB * MAXLEN * DIM];
__device__ bf16  g_qh[(size_t)BB * MAXLEN * 3 * DIM];
__device__ bf16  g_ql[(size_t)BB * MAXLEN * 3 * DIM];
__device__ bf16  g_Hh[(size_t)BB * MAXLEN * 4 * DIM];
__device__ bf16  g_Hl[(size_t)BB * MAXLEN * 4 * DIM];
__device__ bf16  g_Ah[(size_t)BB * MAXLEN * DIM];
__device__ bf16  g_Al[(size_t)BB * MAXLEN * DIM];
__device__ float g_S[(size_t)BB * NHH * MAXLEN * MAXLEN];
__device__ bf16  g_Ph[(size_t)BB * NHH * MAXLEN * MAXLEN];
__device__ bf16  g_Pl[(size_t)BB * NHH * MAXLEN * MAXLEN];
__device__ bf16  g_Vth[(size_t)BB * NHH * HD * MAXLEN];
__device__ bf16  g_Vtl[(size_t)BB * NHH * HD * MAXLEN];
__device__ bf16  g_Wth[(size_t)2 * WLAYER];
__device__ bf16  g_Wtl[(size_t)2 * WLAYER];
__device__ int   g_cnt[BB];
__device__ int   g_L[BB];
__device__ int   g_rc[BB * MAXP];
__device__ float g_dep[BB * MAXP];

__device__ __forceinline__ float gelu_f(float x) {
    return 0.5f * x * (1.0f + erff(x * 0.7071067811865475f));
}
__device__ __forceinline__ u32 s2u(const void* p) {
    u32 a;
    asm("{ .reg .u64 t; cvta.to.shared.u64 t, %1; cvt.u32.u64 %0, t; }" : "=r"(a) : "l"(p));
    return a;
}
__device__ __forceinline__ void cpa(u32 s, const void* g) {
    asm volatile("cp.async.cg.shared.global [%0], [%1], 16;" :: "r"(s), "l"(g));
}
#define CPC() asm volatile("cp.async.commit_group;" ::: "memory")
__device__ __forceinline__ void ldm4(u32& r0, u32& r1, u32& r2, u32& r3, u32 a) {
    asm volatile("ldmatrix.sync.aligned.m8n8.x4.shared.b16 {%0,%1,%2,%3}, [%4];"
        : "=r"(r0), "=r"(r1), "=r"(r2), "=r"(r3) : "r"(a));
}
__device__ __forceinline__ void mma16816(float* c, const u32* a, const u32* b) {
    asm volatile("mma.sync.aligned.m16n8k16.row.col.f32.bf16.bf16.f32 "
        "{%0,%1,%2,%3},{%4,%5,%6,%7},{%8,%9},{%0,%1,%2,%3};"
        : "+f"(c[0]), "+f"(c[1]), "+f"(c[2]), "+f"(c[3])
        : "r"(a[0]), "r"(a[1]), "r"(a[2]), "r"(a[3]), "r"(b[0]), "r"(b[1]));
}

/* stage: Ah@0, Al@10240, Bh@20480, Bl@30720; rows padded to 80B (40 bf16) */
#define STG 40960u
#define SMEMSZ (2 * 40960)

__device__ __forceinline__ void load_chunk(u32 sb,
    const bf16* Ah, const bf16* Al, size_t sA,
    const bf16* Bh, const bf16* Bl, size_t sB, size_t k0)
{
    int tid = threadIdx.x;
    #pragma unroll
    for (int j = 0; j < 2; j++) {
        int e = tid + j * 256;
        int row = e >> 2, kq = (e & 3) * 8;
        u32 so = (u32)(row * 80 + kq * 2);
        size_t ga = (size_t)row * sA + k0 + kq;
        size_t gb = (size_t)row * sB + k0 + kq;
        cpa(sb + so, Ah + ga);
        cpa(sb + 10240 + so, Al + ga);
        cpa(sb + 20480 + so, Bh + gb);
        cpa(sb + 30720 + so, Bl + gb);
    }
}

__device__ __forceinline__ void gemm_core(u32 sb,
    const bf16* Ah, const bf16* Al, size_t sA,
    const bf16* Bh, const bf16* Bl, size_t sB,
    int nch, float acc[4][4][4])
{
    int tid = threadIdx.x, wid = tid >> 5, lane = tid & 31;
    int wm = (wid >> 2) * 64, wn = (wid & 3) * 32;
    load_chunk(sb, Ah, Al, sA, Bh, Bl, sB, 0);
    CPC();
    for (int c = 0; c < nch; c++) {
        if (c + 1 < nch) {
            load_chunk(sb + (u32)((c + 1) & 1) * STG, Ah, Al, sA, Bh, Bl, sB, (size_t)(c + 1) * 32);
            CPC();
            asm volatile("cp.async.wait_group 1;" ::: "memory");
        } else {
            asm volatile("cp.async.wait_group 0;" ::: "memory");
        }
        __syncthreads();
        u32 st = sb + (u32)(c & 1) * STG;
        #pragma unroll
        for (int ks = 0; ks < 2; ks++) {
            u32 ah[4][4], al[4][4], bh[4][2], bl[4][2];
            int arow = wm + (lane & 15);
            u32 acb = (u32)(ks * 32 + (lane >> 4) * 16);
            #pragma unroll
            for (int mf = 0; mf < 4; mf++) {
                u32 ad = st + (u32)((arow + mf * 16) * 80) + acb;
                ldm4(ah[mf][0], ah[mf][1], ah[mf][2], ah[mf][3], ad);
                ldm4(al[mf][0], al[mf][1], al[mf][2], al[mf][3], ad + 10240);
            }
            int g = lane >> 3;
            int brow = wn + ((g & 2) ? 8 : 0) + (lane & 7);
            u32 bcb = (u32)(ks * 32 + (g & 1) * 16);
            #pragma unroll
            for (int p = 0; p < 2; p++) {
                u32 bd = st + 20480 + (u32)((brow + p * 16) * 80) + bcb;
                u32 r0, r1, r2, r3;
                ldm4(r0, r1, r2, r3, bd);
                bh[2 * p][0] = r0; bh[2 * p][1] = r1;
                bh[2 * p + 1][0] = r2; bh[2 * p + 1][1] = r3;
                ldm4(r0, r1, r2, r3, bd + 10240);
                bl[2 * p][0] = r0; bl[2 * p][1] = r1;
                bl[2 * p + 1][0] = r2; bl[2 * p + 1][1] = r3;
            }
            #pragma unroll
            for (int mf = 0; mf < 4; mf++)
                #pragma unroll
                for (int nf = 0; nf < 4; nf++) {
                    mma16816(acc[mf][nf], ah[mf], bh[nf]);
                    mma16816(acc[mf][nf], al[mf], bh[nf]);
                    mma16816(acc[mf][nf], ah[mf], bl[nf]);
                }
        }
        __syncthreads();
    }
}

/* MODE 0: pair+bias  1: pair+bias+gelu  2: fp32 residual add into Xres */
template <int MODE>
__global__ __launch_bounds__(256, 1) void tgemm(
    const bf16* __restrict__ Ah, const bf16* __restrict__ Al, int sA,
    const bf16* __restrict__ Wth, const bf16* __restrict__ Wtl,
    const float* __restrict__ bias, int K,
    bf16* __restrict__ Oh, bf16* __restrict__ Ol,
    float* __restrict__ Xres, int strideO)
{
    extern __shared__ __align__(16) char sm[];
    u32 sb = s2u(sm);
    int by = blockIdx.y;
    int b = by / RTPB, local = (by % RTPB) * 128;
    if (local >= g_L[b]) return;
    int col0 = blockIdx.x * 128;
    float acc[4][4][4];
    #pragma unroll
    for (int i = 0; i < 4; i++)
        #pragma unroll
        for (int j = 0; j < 4; j++)
            acc[i][j][0] = acc[i][j][1] = acc[i][j][2] = acc[i][j][3] = 0.f;
    gemm_core(sb, Ah + (size_t)(b * MAXLEN + local) * sA,
              Al + (size_t)(b * MAXLEN + local) * sA, (size_t)sA,
              Wth + (size_t)col0 * K, Wtl + (size_t)col0 * K, (size_t)K, K / 32, acc);
    int tid = threadIdx.x, wid = tid >> 5, lane = tid & 31;
    int wm = (wid >> 2) * 64, wn = (wid & 3) * 32;
    int r = lane >> 2, c2 = (lane & 3) * 2;
    #pragma unroll
    for (int mf = 0; mf < 4; mf++)
        #pragma unroll
        for (int nf = 0; nf < 4; nf++) {
            int n = col0 + wn + nf * 8 + c2;
            #pragma unroll
            for (int hr = 0; hr < 2; hr++) {
                int row = local + wm + mf * 16 + r + hr * 8;
                float v0 = acc[mf][nf][hr * 2]     + bias[n];
                float v1 = acc[mf][nf][hr * 2 + 1] + bias[n + 1];
                size_t o = (size_t)(b * MAXLEN + row) * strideO + n;
                if (MODE == 2) {
                    float2 old = *(float2*)(Xres + o);
                    ((float2*)(Xres + o))[0] = make_float2(v0 + old.x, v1 + old.y);
                } else {
                    if (MODE == 1) { v0 = gelu_f(v0); v1 = gelu_f(v1); }
                    bf16 h0 = __float2bfloat16(v0), h1 = __float2bfloat16(v1);
                    __nv_bfloat162 hp, lp;
                    hp.x = h0; hp.y = h1;
                    lp.x = __float2bfloat16(v0 - __bfloat162float(h0));
                    lp.y = __float2bfloat16(v1 - __bfloat162float(h1));
                    *(__nv_bfloat162*)(Oh + o) = hp;
                    *(__nv_bfloat162*)(Ol + o) = lp;
                }
            }
        }
}

__global__ __launch_bounds__(256, 1) void scores_mma() {
    extern __shared__ __align__(16) char sm[];
    u32 sb = s2u(sm);
    int bh = blockIdx.z, b = bh >> 2, h = bh & 3;
    int L = g_L[b];
    int n0 = blockIdx.y * 128; if (n0 >= L) return;
    int m0 = blockIdx.x * 128; if (m0 >= L) return;
    float acc[4][4][4];
    #pragma unroll
    for (int i = 0; i < 4; i++)
        #pragma unroll
        for (int j = 0; j < 4; j++)
            acc[i][j][0] = acc[i][j][1] = acc[i][j][2] = acc[i][j][3] = 0.f;
    size_t qo = (size_t)(b * MAXLEN + n0) * 3072 + h * HD;
    size_t ko = (size_t)(b * MAXLEN + m0) * 3072 + 1024 + h * HD;
    gemm_core(sb, g_qh + qo, g_ql + qo, 3072, g_qh + ko, g_ql + ko, 3072, HD / 32, acc);
    int tid = threadIdx.x, wid = tid >> 5, lane = tid & 31;
    int wm = (wid >> 2) * 64, wn = (wid & 3) * 32;
    int r = lane >> 2, c2 = (lane & 3) * 2;
    #pragma unroll
    for (int mf = 0; mf < 4; mf++)
        #pragma unroll
        for (int nf = 0; nf < 4; nf++) {
            int m = m0 + wn + nf * 8 + c2;
            #pragma unroll
            for (int hr = 0; hr < 2; hr++) {
                int n = n0 + wm + mf * 16 + r + hr * 8;
                float* sp = g_S + ((size_t)bh * MAXLEN + n) * MAXLEN + m;
                ((float2*)sp)[0] = make_float2(acc[mf][nf][hr * 2] * 0.0625f,
                                               acc[mf][nf][hr * 2 + 1] * 0.0625f);
            }
        }
}

__global__ __launch_bounds__(256, 1) void av_mma() {
    extern __shared__ __align__(16) char sm[];
    u32 sb = s2u(sm);
    int bh = blockIdx.z, b = bh >> 2, h = bh & 3;
    int L = g_L[b];
    int n0 = blockIdx.y * 128; if (n0 >= L) return;
    int col0 = blockIdx.x * 128;
    int nch = (L + 31) >> 5;
    float acc[4][4][4];
    #pragma unroll
    for (int i = 0; i < 4; i++)
        #pragma unroll
        for (int j = 0; j < 4; j++)
            acc[i][j][0] = acc[i][j][1] = acc[i][j][2] = acc[i][j][3] = 0.f;
    size_t po = ((size_t)bh * MAXLEN + n0) * MAXLEN;
    size_t vo = ((size_t)bh * HD + col0) * MAXLEN;
    gemm_core(sb, g_Ph + po, g_Pl + po, MAXLEN, g_Vth + vo, g_Vtl + vo, MAXLEN, nch, acc);
    int tid = threadIdx.x, wid = tid >> 5, lane = tid & 31;
    int wm = (wid >> 2) * 64, wn = (wid & 3) * 32;
    int r = lane >> 2, c2 = (lane & 3) * 2;
    #pragma unroll
    for (int mf = 0; mf < 4; mf++)
        #pragma unroll
        for (int nf = 0; nf < 4; nf++) {
            int d = col0 + wn + nf * 8 + c2;
            #pragma unroll
            for (int hr = 0; hr < 2; hr++) {
                int row = n0 + wm + mf * 16 + r + hr * 8;
                float v0 = acc[mf][nf][hr * 2], v1 = acc[mf][nf][hr * 2 + 1];
                bf16 h0 = __float2bfloat16(v0), h1 = __float2bfloat16(v1);
                __nv_bfloat162 hp, lp;
                hp.x = h0; hp.y = h1;
                lp.x = __float2bfloat16(v0 - __bfloat162float(h0));
                lp.y = __float2bfloat16(v1 - __bfloat162float(h1));
                size_t o = (size_t)(b * MAXLEN + row) * DIM + h * HD + d;
                *(__nv_bfloat162*)(g_Ah + o) = hp;
                *(__nv_bfloat162*)(g_Al + o) = lp;
            }
        }
}

/* -------------------------- non-tensor kernels ----------------------------- */
__global__ void scan_prompts(const int* __restrict__ m0, const float* __restrict__ dp0) {
    int b = blockIdx.x;
    const int* m = m0 + b * MASKN;
    const float* dp = dp0 + b * MASKN;
    int tid = threadIdx.x, lane = tid & 31, w = tid >> 5;
    __shared__ int wsum[8];
    __shared__ int base;
    if (tid == 0) base = 0;
    __syncthreads();
    for (int c0 = 0; c0 < MASKN; c0 += 256) {
        int idx = c0 + tid;
        int pred = (m[idx] > 0) ? 1 : 0;
        unsigned bal = __ballot_sync(0xffffffffu, pred);
        if (lane == 0) wsum[w] = __popc(bal);
        __syncthreads();
        int woff = base;
        for (int ww = 0; ww < w; ww++) woff += wsum[ww];
        if (pred) {
            int pos = woff + __popc(bal & ((1u << lane) - 1u));
            g_rc[b * MAXP + pos] = idx;
            g_dep[b * MAXP + pos] = dp[idx];
        }
        __syncthreads();
        if (tid == 0) {
            int t = 0;
            for (int ww = 0; ww < 8; ww++) t += wsum[ww];
            base += t;
        }
        __syncthreads();
    }
    if (tid == 0) { g_cnt[b] = base; g_L[b] = 1025 + base; }
}

__global__ __launch_bounds__(256) void init_query(const float* __restrict__ img,
                                                  const float* __restrict__ gauss) {
    int t = blockIdx.x, b = blockIdx.y, tid = threadIdx.x;
    float cx = 2.f * ((float)(t & 31) + 0.5f) / 32.f - 1.f;
    float cy = 2.f * ((float)(t >> 5) + 0.5f) / 32.f - 1.f;
    const float* ib = img + ((size_t)b * 1024 + t) * DIM;
    float* xr = g_X + ((size_t)b * MAXLEN + t) * DIM;
    #pragma unroll
    for (int p = 0; p < 2; p++) {
        int k = tid + p * 256;
        float vv = 6.283185307179586f * (cx * gauss[k] + cy * gauss[512 + k]);
        float sv, cv;
        sincosf(vv, &sv, &cv);
        xr[k] = ib[k] + sv;
        xr[k + 512] = ib[k + 512] + cv;
    }
}

__global__ __launch_bounds__(256) void prompt_rows(const float* __restrict__ gauss,
    const float* __restrict__ w1, const float* __restrict__ b1,
    const float* __restrict__ w2, const float* __restrict__ b2) {
    int b = blockIdx.y;
    int cnt = g_cnt[b];
    int j0 = blockIdx.x * PPB;
    if (j0 >= cnt) return;
    int na = cnt - j0; if (na > PPB) na = PPB;
    __shared__ float h[PPB][512];
    __shared__ float cxs[PPB], cys[PPB];
    int tid = threadIdx.x;
    if (tid < PPB) {
        float cx = 0.f, cy = 0.f;
        if (tid < na) {
            int rc = g_rc[b * MAXP + j0 + tid];
            cx = 2.f * ((float)(rc % 48) + 0.5f) / 48.f - 1.f;
            cy = 2.f * ((float)(rc / 48) + 0.5f) / 48.f - 1.f;
        }
        cxs[tid] = cx; cys[tid] = cy;
    }
    for (int e = tid; e < PPB * 512; e += 256) {
        int q = e >> 9, k = e & 511;
        float d = (q < na) ? g_dep[b * MAXP + j0 + q] : 0.f;
        h[q][k] = gelu_f(fmaf(d, w1[k], b1[k]));
    }
    __syncthreads();
    float* xr = g_X + ((size_t)b * MAXLEN + 1025 + j0) * DIM;
    #pragma unroll
    for (int p = 0; p < 4; p++) {
        int c = tid + p * 256;
        int kc = c & 511;
        float g0 = gauss[kc], g1 = gauss[512 + kc];
        float bb = b2[c];
        float acc[PPB];
        #pragma unroll
        for (int q = 0; q < PPB; q++) {
            float vv = 6.283185307179586f * (cxs[q] * g0 + cys[q] * g1);
            acc[q] = bb + ((c < 512) ? sinf(vv) : cosf(vv));
        }
        for (int k = 0; k < 512; k++) {
            float wv = w2[k * 1024 + c];
            #pragma unroll
            for (int q = 0; q < PPB; q++) acc[q] = fmaf(h[q][k], wv, acc[q]);
        }
        for (int q = 0; q < na; q++) xr[(size_t)q * DIM + c] = acc[q];
    }
}

__global__ void sep_kernel(const float* __restrict__ sep) {
    int b = blockIdx.x, tid = threadIdx.x;
    float* xr = g_X + ((size_t)b * MAXLEN + 1024) * DIM;
    #pragma unroll
    for (int p = 0; p < 4; p++) xr[tid + p * 256] = sep[tid + p * 256];
}

__device__ __forceinline__ float brsum(float v, float* sh) {
    int tid = threadIdx.x, lane = tid & 31, w = tid >> 5;
    #pragma unroll
    for (int o = 16; o > 0; o >>= 1) v += __shfl_xor_sync(0xffffffffu, v, o);
    if (lane == 0) sh[w] = v;
    __syncthreads();
    float r = sh[0] + sh[1] + sh[2] + sh[3] + sh[4] + sh[5] + sh[6] + sh[7];
    __syncthreads();
    return r;
}

__global__ __launch_bounds__(256) void ln_kernel(const float* __restrict__ w,
                                                 const float* __restrict__ bs) {
    int t = blockIdx.x, b = blockIdx.y;
    if (t >= g_L[b]) return;
    __shared__ float sh[8];
    const float* xr = g_X + ((size_t)b * MAXLEN + t) * DIM;
    size_t yo = ((size_t)b * MAXLEN + t) * DIM;
    int tid = threadIdx.x;
    float4 v = ((const float4*)xr)[tid];
    float s = brsum(v.x + v.y + v.z + v.w, sh);
    float m = s * (1.f / 1024.f);
    float4 dv = make_float4(v.x - m, v.y - m, v.z - m, v.w - m);
    float vs = brsum(dv.x * dv.x + dv.y * dv.y + dv.z * dv.z + dv.w * dv.w, sh);
    float rs = rsqrtf(vs * (1.f / 1024.f) + 1e-5f);
    float4 wv = ((const float4*)w)[tid];
    float4 bv = ((const float4*)bs)[tid];
    float o[4] = {dv.x * rs * wv.x + bv.x, dv.y * rs * wv.y + bv.y,
                  dv.z * rs * wv.z + bv.z, dv.w * rs * wv.w + bv.w};
    #pragma unroll
    for (int e = 0; e < 4; e++) {
        bf16 hh = __float2bfloat16(o[e]);
        g_Yh[yo + tid * 4 + e] = hh;
        g_Yl[yo + tid * 4 + e] = __float2bfloat16(o[e] - __bfloat162float(hh));
    }
}

__global__ __launch_bounds__(256) void softmax_kernel() {
    int n = blockIdx.x, h = blockIdx.y, b = blockIdx.z;
    int L = g_L[b];
    if (n >= L) return;
    int Lpad = (L + 63) & ~63;
    __shared__ float sh[8];
    size_t off = ((size_t)(b * NHH + h) * MAXLEN + n) * MAXLEN;
    const float* sr = g_S + off;
    int tid = threadIdx.x, lane = tid & 31, w = tid >> 5;
    float v[SMX_IT];
    float mx = -3e38f;
    #pragma unroll
    for (int i = 0; i < SMX_IT; i++) {
        int m = tid + i * 256;
        v[i] = (m < L) ? sr[m] : -3e38f;
        mx = fmaxf(mx, v[i]);
    }
    #pragma unroll
    for (int o = 16; o > 0; o >>= 1) mx = fmaxf(mx, __shfl_xor_sync(0xffffffffu, mx, o));
    if (lane == 0) sh[w] = mx;
    __syncthreads();
    mx = fmaxf(fmaxf(fmaxf(sh[0], sh[1]), fmaxf(sh[2], sh[3])),
               fmaxf(fmaxf(sh[4], sh[5]), fmaxf(sh[6], sh[7])));
    __syncthreads();
    float sum = 0.f;
    #pragma unroll
    for (int i = 0; i < SMX_IT; i++) { v[i] = expf(v[i] - mx); sum += v[i]; }
    sum = brsum(sum, sh);
    float inv = 1.f / sum;
    #pragma unroll
    for (int i = 0; i < SMX_IT; i++) {
        int m = tid + i * 256;
        if (m < Lpad) {
            float p = (m < L) ? v[i] * inv : 0.f;
            bf16 hh = __float2bfloat16(p);
            g_Ph[off + m] = hh;
            g_Pl[off + m] = __float2bfloat16(p - __bfloat162float(hh));
        }
    }
}

__global__ __launch_bounds__(256) void vtrans() {
    __shared__ bf16 th[32][33], tl[32][33];
    int mt = blockIdx.x * 32, dt = blockIdx.y * 32, bh = blockIdx.z;
    int b = bh >> 2, h = bh & 3;
    int L = g_L[b];
    int tx = threadIdx.x & 31, ty = threadIdx.x >> 5;
    #pragma unroll
    for (int i = 0; i < 4; i++) {
        int m = mt + ty + i * 8, d = dt + tx;
        size_t o = (size_t)(b * MAXLEN + m) * 3072 + 2048 + h * HD + d;
        th[ty + i * 8][tx] = g_qh[o];
        tl[ty + i * 8][tx] = g_ql[o];
    }
    __syncthreads();
    #pragma unroll
    for (int i = 0; i < 4; i++) {
        int d = dt + ty + i * 8, m = mt + tx;
        size_t o = ((size_t)bh * HD + d) * MAXLEN + m;
        bf16 z = __float2bfloat16(0.f);
        bool ok = (m < L);
        g_Vth[o] = ok ? th[tx][ty + i * 8] : z;
        g_Vtl[o] = ok ? tl[tx][ty + i * 8] : z;
    }
}

__global__ __launch_bounds__(256) void wtrans(const float* __restrict__ src,
                                              bf16* __restrict__ dh, bf16* __restrict__ dl,
                                              int K, int N) {
    __shared__ float t[32][33];
    int nt = blockIdx.x * 32, kt = blockIdx.y * 32;
    int tx = threadIdx.x & 31, ty = threadIdx.x >> 5;
    #pragma unroll
    for (int i = 0; i < 4; i++)
        t[ty + i * 8][tx] = src[(size_t)(kt + ty + i * 8) * N + nt + tx];
    __syncthreads();
    #pragma unroll
    for (int i = 0; i < 4; i++) {
        float v = t[tx][ty + i * 8];
        size_t o = (size_t)(nt + ty + i * 8) * K + kt + tx;
        bf16 hh = __float2bfloat16(v);
        dh[o] = hh;
        dl[o] = __float2bfloat16(v - __bfloat162float(hh));
    }
}

__global__ void out_copy(const float* __restrict__ img, float* __restrict__ out) {
    int t = blockIdx.x, b = blockIdx.y, tid = threadIdx.x;
    const float* src = (g_cnt[b] == 0) ? img + ((size_t)b * 1024 + t) * DIM
                                       : g_X + ((size_t)b * MAXLEN + t) * DIM;
    ((float4*)(out + ((size_t)b * 1024 + t) * DIM))[tid] = ((const float4*)src)[tid];
}

extern "C" void kernel_launch(void* const* d_in, const int* in_sizes, int n_in,
                              void* d_out, int out_size) {
    const float* img   = (const float*)d_in[0];
    const float* depth = (const float*)d_in[1];
    const int*   mask  = (const int*)d_in[2];
    const float* gauss = (const float*)d_in[5];
    const float* w1    = (const float*)d_in[6];
    const float* b1    = (const float*)d_in[7];
    const float* w2    = (const float*)d_in[8];
    const float* b2    = (const float*)d_in[9];
    const float* sep   = (const float*)d_in[10];
    const float* ln1w  = (const float*)d_in[11];
    const float* ln1b  = (const float*)d_in[12];
    const float* qkvw  = (const float*)d_in[13];
    const float* qkvb  = (const float*)d_in[14];
    const float* projw = (const float*)d_in[15];
    const float* projb = (const float*)d_in[16];
    const float* ln2w  = (const float*)d_in[17];
    const float* ln2b  = (const float*)d_in[18];
    const float* mw1   = (const float*)d_in[19];
    const float* mb1   = (const float*)d_in[20];
    const float* mw2   = (const float*)d_in[21];
    const float* mb2   = (const float*)d_in[22];
    float* out = (float*)d_out;

    bf16 *pWth, *pWtl, *pYh, *pYl, *pHh, *pHl, *pAh, *pAl;
    float* pX;
    cudaGetSymbolAddress((void**)&pWth, g_Wth);
    cudaGetSymbolAddress((void**)&pWtl, g_Wtl);
    cudaGetSymbolAddress((void**)&pYh, g_Yh);
    cudaGetSymbolAddress((void**)&pYl, g_Yl);
    cudaGetSymbolAddress((void**)&pHh, g_Hh);
    cudaGetSymbolAddress((void**)&pHl, g_Hl);
    cudaGetSymbolAddress((void**)&pAh, g_Ah);
    cudaGetSymbolAddress((void**)&pAl, g_Al);
    cudaGetSymbolAddress((void**)&pX, g_X);
    bf16 *pqh, *pql;
    cudaGetSymbolAddress((void**)&pqh, g_qh);
    cudaGetSymbolAddress((void**)&pql, g_ql);

    cudaFuncSetAttribute(tgemm<0>, cudaFuncAttributeMaxDynamicSharedMemorySize, SMEMSZ);
    cudaFuncSetAttribute(tgemm<1>, cudaFuncAttributeMaxDynamicSharedMemorySize, SMEMSZ);
    cudaFuncSetAttribute(tgemm<2>, cudaFuncAttributeMaxDynamicSharedMemorySize, SMEMSZ);
    cudaFuncSetAttribute(scores_mma, cudaFuncAttributeMaxDynamicSharedMemorySize, SMEMSZ);
    cudaFuncSetAttribute(av_mma, cudaFuncAttributeMaxDynamicSharedMemorySize, SMEMSZ);

    scan_prompts<<<BB, 256>>>(mask, depth);
    init_query<<<dim3(1024, BB), 256>>>(img, gauss);
    prompt_rows<<<dim3(MAXP / PPB, BB), 256>>>(gauss, w1, b1, w2, b2);
    for (int i = 0; i < 2; i++) {
        size_t wb = (size_t)i * WLAYER;
        wtrans<<<dim3(96, 32), 256>>>(qkvw + (size_t)i * 1024 * 3072, pWth + wb, pWtl + wb, 1024, 3072);
        wtrans<<<dim3(32, 32), 256>>>(projw + (size_t)i * 1024 * 1024, pWth + wb + 3145728, pWtl + wb + 3145728, 1024, 1024);
        wtrans<<<dim3(128, 32), 256>>>(mw1 + (size_t)i * 1024 * 4096, pWth + wb + 4194304, pWtl + wb + 4194304, 1024, 4096);
        wtrans<<<dim3(32, 128), 256>>>(mw2 + (size_t)i * 4096 * 1024, pWth + wb + 8388608, pWtl + wb + 8388608, 4096, 1024);
    }
    const int RT = BB * RTPB;
    for (int i = 0; i < 2; i++) {
        size_t wb = (size_t)i * WLAYER;
        sep_kernel<<<BB, 256>>>(sep + (size_t)i * DIM);
        ln_kernel<<<dim3(MAXLEN, BB), 256>>>(ln1w + i * DIM, ln1b + i * DIM);
        tgemm<0><<<dim3(24, RT), 256, SMEMSZ>>>(pYh, pYl, 1024, pWth + wb, pWtl + wb,
                                                qkvb + i * 3072, 1024, pqh, pql, 0, 3072);
        vtrans<<<dim3(MAXLEN / 32, HD / 32, BB * NHH), 256>>>();
        scores_mma<<<dim3(28, 28, BB * NHH), 256, SMEMSZ>>>();
        softmax_kernel<<<dim3(MAXLEN, NHH, BB), 256>>>();
        av_mma<<<dim3(2, 28, BB * NHH), 256, SMEMSZ>>>();
        tgemm<2><<<dim3(8, RT), 256, SMEMSZ>>>(pAh, pAl, 1024, pWth + wb + 3145728, pWtl + wb + 3145728,
                                               projb + i * DIM, 1024, 0, 0, pX, 1024);
        ln_kernel<<<dim3(MAXLEN, BB), 256>>>(ln2w + i * DIM, ln2b + i * DIM);
        tgemm<1><<<dim3(32, RT), 256, SMEMSZ>>>(pYh, pYl, 1024, pWth + wb + 4194304, pWtl + wb + 4194304,
                                                mb1 + i * 4096, 1024, pHh, pHl, 0, 4096);
        tgemm<2><<<dim3(8, RT), 256, SMEMSZ>>>(pHh, pHl, 4096, pWth + wb + 8388608, pWtl + wb + 8388608,
                                               mb2 + i * DIM, 4096, 0, 0, pX, 1024);
    }
    out_copy<<<dim3(1024, BB), 256>>>(img, out);
}